// round 1
// baseline (speedup 1.0000x reference)
#include <cuda_runtime.h>
#include <math.h>

// Problem constants
#define BB 4
#define SS 2048
#define DD 2048
#define DI 1024
#define MM (BB*SS)        // 8192
#define D4 (DD/4)         // 512

// GEMM tiling
#define BM 128
#define BN 128
#define BK 16

// ---------------- scratch (device globals; no allocation allowed) ----------
__device__ float g_x2[(size_t)MM * DD];   // x after short-conv residual
__device__ float g_h [(size_t)MM * DD];   // h after GEMM1+gelu; reused as y
__device__ float g_fs[(size_t)MM * 3];    // per-(b,s) filt sums
__device__ float g_w [BB * 3];            // final per-batch conv weights

__device__ __forceinline__ float geluf(float v) {
    return 0.5f * v * (1.0f + erff(v * 0.70710678118654752f));
}

// ---------------- kernel 1: causal depthwise short conv + residual --------
__global__ void shortconv_kernel(const float* __restrict__ x,
                                 const float* __restrict__ sw,
                                 const float* __restrict__ sb)
{
    int idx = blockIdx.x * blockDim.x + threadIdx.x;
    if (idx >= BB * SS * D4) return;
    int d4 = idx % D4;
    int bs = idx / D4;
    int s  = bs & (SS - 1);
    int d  = d4 * 4;
    size_t base = (size_t)bs * DD + d;

    float4 xc = *(const float4*)(x + base);
    float4 x1 = (s >= 1) ? *(const float4*)(x + base - DD)     : make_float4(0.f,0.f,0.f,0.f);
    float4 x0 = (s >= 2) ? *(const float4*)(x + base - 2*DD)   : make_float4(0.f,0.f,0.f,0.f);

    float4 o;
    {
        float w0 = sw[(d+0)*3+0], w1 = sw[(d+0)*3+1], w2 = sw[(d+0)*3+2];
        o.x = xc.x + sb[d+0] + x0.x*w0 + x1.x*w1 + xc.x*w2;
    }
    {
        float w0 = sw[(d+1)*3+0], w1 = sw[(d+1)*3+1], w2 = sw[(d+1)*3+2];
        o.y = xc.y + sb[d+1] + x0.y*w0 + x1.y*w1 + xc.y*w2;
    }
    {
        float w0 = sw[(d+2)*3+0], w1 = sw[(d+2)*3+1], w2 = sw[(d+2)*3+2];
        o.z = xc.z + sb[d+2] + x0.z*w0 + x1.z*w1 + xc.z*w2;
    }
    {
        float w0 = sw[(d+3)*3+0], w1 = sw[(d+3)*3+1], w2 = sw[(d+3)*3+2];
        o.w = xc.w + sb[d+3] + x0.w*w0 + x1.w*w1 + xc.w*w2;
    }
    *(float4*)(g_x2 + base) = o;
}

// ---------------- tiled fp32 GEMM: C = (A @ W) + bias, optional GELU ------
// A: MxK row-major, W: KxN row-major, C: MxN row-major. M,N,K all % tile == 0.
template<int GELU>
__global__ void __launch_bounds__(256)
gemm_bias_act(const float* __restrict__ A, const float* __restrict__ W,
              const float* __restrict__ bias, float* __restrict__ C)
{
    const int K = DD, N = DD;
    __shared__ float As[2][BK][BM + 4];
    __shared__ float Bs[2][BK][BN];

    const int tid = threadIdx.x;
    const int bm  = blockIdx.y;
    const int bn  = blockIdx.x;

    const float* Ablk = A + (size_t)bm * BM * K;
    const float* Bblk = W + (size_t)bn * BN;

    // global->smem staging layout
    const int am  = tid >> 2;          // 0..63 (row in tile, +64 for 2nd)
    const int ak  = (tid & 3) << 2;    // 0,4,8,12
    const int bk  = tid >> 5;          // 0..7 (k row, +8 for 2nd)
    const int bn4 = (tid & 31) << 2;   // 0..124

    float4 ra0, ra1, rb0, rb1;

    // prologue: tile 0
    ra0 = *(const float4*)(Ablk + (size_t)am      * K + ak);
    ra1 = *(const float4*)(Ablk + (size_t)(am+64) * K + ak);
    rb0 = *(const float4*)(Bblk + (size_t)bk      * N + bn4);
    rb1 = *(const float4*)(Bblk + (size_t)(bk+8)  * N + bn4);

    As[0][ak+0][am]    = ra0.x; As[0][ak+1][am]    = ra0.y;
    As[0][ak+2][am]    = ra0.z; As[0][ak+3][am]    = ra0.w;
    As[0][ak+0][am+64] = ra1.x; As[0][ak+1][am+64] = ra1.y;
    As[0][ak+2][am+64] = ra1.z; As[0][ak+3][am+64] = ra1.w;
    *(float4*)&Bs[0][bk][bn4]   = rb0;
    *(float4*)&Bs[0][bk+8][bn4] = rb1;
    __syncthreads();

    const int m0 = (tid >> 4) << 3;    // 0..120 step 8
    const int n0 = (tid & 15) << 3;    // 0..120 step 8

    float acc[8][8];
    #pragma unroll
    for (int i = 0; i < 8; i++)
        #pragma unroll
        for (int j = 0; j < 8; j++) acc[i][j] = 0.f;

    const int nt = K / BK;  // 128
    for (int t = 0; t < nt; ++t) {
        const int cur = t & 1;
        const int nxt = cur ^ 1;

        if (t + 1 < nt) {
            const float* Ab = Ablk + (t + 1) * BK;
            const float* Bb = Bblk + (size_t)(t + 1) * BK * N;
            ra0 = *(const float4*)(Ab + (size_t)am      * K + ak);
            ra1 = *(const float4*)(Ab + (size_t)(am+64) * K + ak);
            rb0 = *(const float4*)(Bb + (size_t)bk      * N + bn4);
            rb1 = *(const float4*)(Bb + (size_t)(bk+8)  * N + bn4);
        }

        #pragma unroll
        for (int kk = 0; kk < BK; ++kk) {
            float av[8], bv[8];
            *(float4*)&av[0] = *(const float4*)&As[cur][kk][m0];
            *(float4*)&av[4] = *(const float4*)&As[cur][kk][m0 + 4];
            *(float4*)&bv[0] = *(const float4*)&Bs[cur][kk][n0];
            *(float4*)&bv[4] = *(const float4*)&Bs[cur][kk][n0 + 4];
            #pragma unroll
            for (int i = 0; i < 8; i++)
                #pragma unroll
                for (int j = 0; j < 8; j++)
                    acc[i][j] += av[i] * bv[j];
        }

        if (t + 1 < nt) {
            As[nxt][ak+0][am]    = ra0.x; As[nxt][ak+1][am]    = ra0.y;
            As[nxt][ak+2][am]    = ra0.z; As[nxt][ak+3][am]    = ra0.w;
            As[nxt][ak+0][am+64] = ra1.x; As[nxt][ak+1][am+64] = ra1.y;
            As[nxt][ak+2][am+64] = ra1.z; As[nxt][ak+3][am+64] = ra1.w;
            *(float4*)&Bs[nxt][bk][bn4]   = rb0;
            *(float4*)&Bs[nxt][bk+8][bn4] = rb1;
        }
        __syncthreads();
    }

    // epilogue: bias (+ gelu), vectorized store
    float bvv[8];
    #pragma unroll
    for (int j = 0; j < 8; j++) bvv[j] = bias[bn * BN + n0 + j];

    #pragma unroll
    for (int i = 0; i < 8; i++) {
        size_t row = (size_t)(bm * BM + m0 + i);
        float* Crow = C + row * N + bn * BN + n0;
        float ov[8];
        #pragma unroll
        for (int j = 0; j < 8; j++) {
            float v = acc[i][j] + bvv[j];
            ov[j] = GELU ? geluf(v) : v;
        }
        *(float4*)&Crow[0] = *(float4*)&ov[0];
        *(float4*)&Crow[4] = *(float4*)&ov[4];
    }
}

// ---------------- kernel 3: filt dots + tanh per (b,s) --------------------
__global__ void filt_kernel(const float* __restrict__ fw,
                            const float* __restrict__ fb)
{
    const int bs = blockIdx.x;                 // 0..8191
    const float* hr = g_h + (size_t)bs * DD;

    float a[6] = {0.f,0.f,0.f,0.f,0.f,0.f};    // [f*3 + k]
    for (int i = threadIdx.x; i < DI; i += blockDim.x) {
        float w0 = fw[i*3+0], w1 = fw[i*3+1], w2 = fw[i*3+2];
        float h0 = hr[i];
        float h1 = hr[i + DI];
        a[0] += h0*w0; a[1] += h0*w1; a[2] += h0*w2;
        a[3] += h1*w0; a[4] += h1*w1; a[5] += h1*w2;
    }
    #pragma unroll
    for (int off = 16; off; off >>= 1)
        #pragma unroll
        for (int q = 0; q < 6; q++)
            a[q] += __shfl_xor_sync(0xffffffffu, a[q], off);

    __shared__ float red[8][6];
    int warp = threadIdx.x >> 5, lane = threadIdx.x & 31;
    if (lane == 0)
        #pragma unroll
        for (int q = 0; q < 6; q++) red[warp][q] = a[q];
    __syncthreads();

    if (threadIdx.x == 0) {
        float t[6];
        #pragma unroll
        for (int q = 0; q < 6; q++) {
            float s = 0.f;
            #pragma unroll
            for (int w = 0; w < 8; w++) s += red[w][q];
            t[q] = s;
        }
        #pragma unroll
        for (int k = 0; k < 3; k++)
            g_fs[(size_t)bs*3 + k] = tanhf(t[k] + fb[k]) + tanhf(t[3+k] + fb[k]);
    }
}

// ---------------- kernel 4: reduce over sequence -> w[b][k] ---------------
__global__ void wreduce_kernel()
{
    const int b = blockIdx.x;
    float a0 = 0.f, a1 = 0.f, a2 = 0.f;
    for (int s = threadIdx.x; s < SS; s += blockDim.x) {
        size_t p = ((size_t)b * SS + s) * 3;
        a0 += g_fs[p+0]; a1 += g_fs[p+1]; a2 += g_fs[p+2];
    }
    #pragma unroll
    for (int off = 16; off; off >>= 1) {
        a0 += __shfl_xor_sync(0xffffffffu, a0, off);
        a1 += __shfl_xor_sync(0xffffffffu, a1, off);
        a2 += __shfl_xor_sync(0xffffffffu, a2, off);
    }
    __shared__ float red[8][3];
    int warp = threadIdx.x >> 5, lane = threadIdx.x & 31;
    if (lane == 0) { red[warp][0] = a0; red[warp][1] = a1; red[warp][2] = a2; }
    __syncthreads();
    if (threadIdx.x == 0) {
        float s0 = 0.f, s1 = 0.f, s2 = 0.f;
        #pragma unroll
        for (int w = 0; w < 8; w++) { s0 += red[w][0]; s1 += red[w][1]; s2 += red[w][2]; }
        const float inv = 1.0f / (float)SS;
        g_w[b*3+0] = s0 * inv;
        g_w[b*3+1] = s1 * inv;
        g_w[b*3+2] = s2 * inv;
    }
}

// ---------------- kernel 5: gated conv * v, gelu -> y (into g_h) ----------
__global__ void convgate_kernel(const float* __restrict__ x)
{
    int idx = blockIdx.x * blockDim.x + threadIdx.x;
    if (idx >= BB * SS * D4) return;
    int d4 = idx % D4;
    int bs = idx / D4;
    int s  = bs & (SS - 1);
    int b  = bs >> 11;
    size_t base = (size_t)bs * DD + d4 * 4;

    float w0 = g_w[b*3+0], w1 = g_w[b*3+1], w2 = g_w[b*3+2];

    float4 c2 = *(const float4*)(g_x2 + base);
    float4 c1 = (s >= 1) ? *(const float4*)(g_x2 + base - DD)   : make_float4(0.f,0.f,0.f,0.f);
    float4 c0 = (s >= 2) ? *(const float4*)(g_x2 + base - 2*DD) : make_float4(0.f,0.f,0.f,0.f);
    float4 v  = *(const float4*)(x + base);

    float4 o;
    o.x = geluf((c0.x*w0 + c1.x*w1 + c2.x*w2) * v.x);
    o.y = geluf((c0.y*w0 + c1.y*w1 + c2.y*w2) * v.y);
    o.z = geluf((c0.z*w0 + c1.z*w1 + c2.z*w2) * v.z);
    o.w = geluf((c0.w*w0 + c1.w*w1 + c2.w*w2) * v.w);
    *(float4*)(g_h + base) = o;   // reuse g_h as y (h no longer needed)
}

// ---------------- launcher -------------------------------------------------
extern "C" void kernel_launch(void* const* d_in, const int* in_sizes, int n_in,
                              void* d_out, int out_size)
{
    const float* x       = (const float*)d_in[0];
    const float* short_w = (const float*)d_in[1];
    const float* short_b = (const float*)d_in[2];
    const float* proj_w  = (const float*)d_in[3];
    const float* proj_b  = (const float*)d_in[4];
    const float* filt_w  = (const float*)d_in[5];
    const float* filt_b  = (const float*)d_in[6];
    const float* out_w   = (const float*)d_in[7];
    const float* out_b   = (const float*)d_in[8];
    float* out = (float*)d_out;

    float *px2 = nullptr, *ph = nullptr;
    cudaGetSymbolAddress((void**)&px2, g_x2);
    cudaGetSymbolAddress((void**)&ph,  g_h);

    const int ethreads = 256;
    const int eblocks  = (BB * SS * D4 + ethreads - 1) / ethreads;  // 16384

    // 1. short conv residual -> g_x2
    shortconv_kernel<<<eblocks, ethreads>>>(x, short_w, short_b);

    // 2. h = gelu(x2 @ proj_w + proj_b) -> g_h
    dim3 ggrid(DD / BN, MM / BM);   // (16, 64)
    gemm_bias_act<1><<<ggrid, 256>>>(px2, proj_w, proj_b, ph);

    // 3. filt dots + tanh per row -> g_fs
    filt_kernel<<<MM, 256>>>(filt_w, filt_b);

    // 4. per-batch mean -> g_w
    wreduce_kernel<<<BB, 256>>>();

    // 5. y = gelu(conv(x2; w) * x) -> g_h (reuse)
    convgate_kernel<<<eblocks, ethreads>>>(x);

    // 6. out = y @ out_w + out_b -> d_out
    gemm_bias_act<0><<<ggrid, 256>>>(ph, out_w, out_b, out);
}

// round 2
// speedup vs baseline: 2.4698x; 2.4698x over previous
#include <cuda_runtime.h>
#include <cuda_bf16.h>
#include <math.h>
#include <stdint.h>

#define BB 4
#define SS 2048
#define DD 2048
#define DI 1024
#define MM (BB*SS)      // 8192
#define KK DD
#define NN DD
#define D4 (DD/4)

// GEMM tiling
#define BM 128
#define BN 128
#define BKK 32
#define ASZ (BM*BKK)    // 4096 bf16 elems per A stage buffer
#define BSZ (BKK*BN)    // 4096

// ---------------- scratch ---------------------------------------------------
__device__ __nv_bfloat16 g_x2h[(size_t)MM*DD];
__device__ __nv_bfloat16 g_x2l[(size_t)MM*DD];
__device__ float         g_h  [(size_t)MM*DD];
__device__ __nv_bfloat16 g_yh [(size_t)MM*DD];
__device__ __nv_bfloat16 g_yl [(size_t)MM*DD];
__device__ __nv_bfloat16 g_pwh[(size_t)KK*NN];
__device__ __nv_bfloat16 g_pwl[(size_t)KK*NN];
__device__ __nv_bfloat16 g_owh[(size_t)KK*NN];
__device__ __nv_bfloat16 g_owl[(size_t)KK*NN];
__device__ float g_fs[(size_t)MM*3];
__device__ float g_w [BB*3];

__device__ __forceinline__ float geluf(float v) {
    return 0.5f * v * (1.0f + erff(v * 0.70710678118654752f));
}
__device__ __forceinline__ void split2(float v, __nv_bfloat16& hi, __nv_bfloat16& lo) {
    hi = __float2bfloat16(v);
    lo = __float2bfloat16(v - __bfloat162float(hi));
}
__device__ __forceinline__ uint32_t smem_u32(const void* p) {
    return (uint32_t)__cvta_generic_to_shared(p);
}

#define CP16(s, g) asm volatile("cp.async.cg.shared.global [%0], [%1], 16;\n" :: "r"(s), "l"(g))
#define CP_COMMIT() asm volatile("cp.async.commit_group;\n")
#define LDSM4(R0,R1,R2,R3,addr) \
    asm volatile("ldmatrix.sync.aligned.m8n8.x4.shared.b16 {%0,%1,%2,%3},[%4];" \
                 : "=r"(R0),"=r"(R1),"=r"(R2),"=r"(R3) : "r"(addr))
#define LDSM2T(R0,R1,addr) \
    asm volatile("ldmatrix.sync.aligned.m8n8.x2.trans.shared.b16 {%0,%1},[%2];" \
                 : "=r"(R0),"=r"(R1) : "r"(addr))
#define MMA16816(D0,D1,D2,D3,A0,A1,A2,A3,B0,B1) \
    asm volatile("mma.sync.aligned.m16n8k16.row.col.f32.bf16.bf16.f32 " \
                 "{%0,%1,%2,%3},{%4,%5,%6,%7},{%8,%9},{%0,%1,%2,%3};" \
                 : "+f"(D0),"+f"(D1),"+f"(D2),"+f"(D3) \
                 : "r"(A0),"r"(A1),"r"(A2),"r"(A3),"r"(B0),"r"(B1))

// ---------------- kernel 1: short conv + residual -> x2 hi/lo --------------
__global__ void shortconv_kernel(const float* __restrict__ x,
                                 const float* __restrict__ sw,
                                 const float* __restrict__ sb)
{
    int idx = blockIdx.x * blockDim.x + threadIdx.x;
    if (idx >= BB * SS * D4) return;
    int d4 = idx % D4;
    int bs = idx / D4;
    int s  = bs & (SS - 1);
    int d  = d4 * 4;
    size_t base = (size_t)bs * DD + d;

    float4 xc = *(const float4*)(x + base);
    float4 x1 = (s >= 1) ? *(const float4*)(x + base - DD)   : make_float4(0.f,0.f,0.f,0.f);
    float4 x0 = (s >= 2) ? *(const float4*)(x + base - 2*DD) : make_float4(0.f,0.f,0.f,0.f);

    float o[4];
    const float xcv[4] = {xc.x, xc.y, xc.z, xc.w};
    const float x1v[4] = {x1.x, x1.y, x1.z, x1.w};
    const float x0v[4] = {x0.x, x0.y, x0.z, x0.w};
    #pragma unroll
    for (int q = 0; q < 4; q++) {
        float w0 = sw[(d+q)*3+0], w1 = sw[(d+q)*3+1], w2 = sw[(d+q)*3+2];
        o[q] = xcv[q] + sb[d+q] + x0v[q]*w0 + x1v[q]*w1 + xcv[q]*w2;
    }
    __nv_bfloat162 h0, h1, l0, l1;
    split2(o[0], h0.x, l0.x); split2(o[1], h0.y, l0.y);
    split2(o[2], h1.x, l1.x); split2(o[3], h1.y, l1.y);
    *(__nv_bfloat162*)(g_x2h + base)     = h0;
    *(__nv_bfloat162*)(g_x2h + base + 2) = h1;
    *(__nv_bfloat162*)(g_x2l + base)     = l0;
    *(__nv_bfloat162*)(g_x2l + base + 2) = l1;
}

// ---------------- weight conversion fp32 -> bf16 hi/lo ---------------------
__global__ void convert_split_kernel(const float* __restrict__ src,
                                     __nv_bfloat16* __restrict__ hi,
                                     __nv_bfloat16* __restrict__ lo, int n4)
{
    int i = blockIdx.x * blockDim.x + threadIdx.x;
    if (i >= n4) return;
    size_t base = (size_t)i * 4;
    float4 v = *(const float4*)(src + base);
    __nv_bfloat162 h0, h1, l0, l1;
    split2(v.x, h0.x, l0.x); split2(v.y, h0.y, l0.y);
    split2(v.z, h1.x, l1.x); split2(v.w, h1.y, l1.y);
    *(__nv_bfloat162*)(hi + base)     = h0;
    *(__nv_bfloat162*)(hi + base + 2) = h1;
    *(__nv_bfloat162*)(lo + base)     = l0;
    *(__nv_bfloat162*)(lo + base + 2) = l1;
}

// ---------------- split-bf16 tensor-core GEMM -------------------------------
// C = (Ahi+Alo) @ (Bhi+Blo) + bias   [drop lo*lo]  + optional GELU
// A: M x K row-major (bf16 hi/lo), B: K x N row-major (bf16 hi/lo), C fp32.
template<int GELU>
__global__ void __launch_bounds__(256)
gemm_split(const __nv_bfloat16* __restrict__ Ahi, const __nv_bfloat16* __restrict__ Alo,
           const __nv_bfloat16* __restrict__ Bhi, const __nv_bfloat16* __restrict__ Blo,
           const float* __restrict__ bias, float* __restrict__ C)
{
    extern __shared__ __nv_bfloat16 sm[];
    __nv_bfloat16* AsH = sm;                       // [2][128][32]
    __nv_bfloat16* AsL = sm + 2*ASZ;
    __nv_bfloat16* BsH = sm + 4*ASZ;               // [2][32][128]
    __nv_bfloat16* BsL = sm + 4*ASZ + 2*BSZ;

    const int tid  = threadIdx.x;
    const int bm   = blockIdx.y, bn = blockIdx.x;
    const int warp = tid >> 5, lane = tid & 31;
    const int mwarp = (warp & 1) * 64;             // 2 warps in M
    const int nwarp = (warp >> 1) * 32;            // 4 warps in N

    // ---- global->smem staging (16B chunks) ----
    const int a_m = tid >> 2;          // 0..63 (row; +64 for 2nd)
    const int a_c = tid & 3;           // chunk 0..3 within 32-elem row
    const int b_k = tid >> 4;          // 0..15 (k row; +16 for 2nd)
    const int b_c = tid & 15;          // chunk 0..15 within 128-elem row

    const __nv_bfloat16* gAh = Ahi + ((size_t)(bm*BM + a_m))*KK + a_c*8;
    const __nv_bfloat16* gAl = Alo + ((size_t)(bm*BM + a_m))*KK + a_c*8;
    const __nv_bfloat16* gBh = Bhi + (size_t)b_k*NN + bn*BN + b_c*8;
    const __nv_bfloat16* gBl = Blo + (size_t)b_k*NN + bn*BN + b_c*8;

    // smem byte offsets (swizzled): A chunk c at (c ^ (m&3)); B chunk c at (c ^ (k&7))
    const int sA0 = (a_m*BKK      + ((a_c ^ (a_m&3))*8)) * 2;
    const int sA1 = ((a_m+64)*BKK + ((a_c ^ (a_m&3))*8)) * 2;   // (m+64)&3 == m&3
    const int sB0 = (b_k*BN       + ((b_c ^ (b_k&7))*8)) * 2;
    const int sB1 = ((b_k+16)*BN  + ((b_c ^ (b_k&7))*8)) * 2;   // (k+16)&7 == k&7

    const uint32_t baseAH = smem_u32(AsH), baseAL = smem_u32(AsL);
    const uint32_t baseBH = smem_u32(BsH), baseBL = smem_u32(BsL);

    auto issue = [&](int stg, int t) {
        const size_t koffA = (size_t)t * BKK;
        const size_t koffB = (size_t)t * BKK * NN;
        uint32_t aH = baseAH + stg*ASZ*2, aL = baseAL + stg*ASZ*2;
        uint32_t bH = baseBH + stg*BSZ*2, bL = baseBL + stg*BSZ*2;
        CP16(aH + sA0, gAh + koffA);
        CP16(aH + sA1, gAh + koffA + (size_t)64*KK);
        CP16(aL + sA0, gAl + koffA);
        CP16(aL + sA1, gAl + koffA + (size_t)64*KK);
        CP16(bH + sB0, gBh + koffB);
        CP16(bH + sB1, gBh + koffB + (size_t)16*NN);
        CP16(bL + sB0, gBl + koffB);
        CP16(bL + sB1, gBl + koffB + (size_t)16*NN);
        CP_COMMIT();
    };

    float acc[4][4][4];
    #pragma unroll
    for (int i = 0; i < 4; i++)
        #pragma unroll
        for (int j = 0; j < 4; j++)
            #pragma unroll
            for (int q = 0; q < 4; q++) acc[i][j][q] = 0.f;

    // per-lane ldmatrix addressing
    const int lr = lane & 15;          // row within 16
    const int hc = lane >> 4;          // high-k-chunk select (A)
    int rowA[4], swzA[4];
    #pragma unroll
    for (int mt = 0; mt < 4; mt++) {
        rowA[mt] = mwarp + mt*16 + lr;
        swzA[mt] = rowA[mt] & 3;
    }
    const int swzB = lr & 7;
    const int ncbase = nwarp >> 3;     // logical 16B chunk base in B row

    const int NT = KK / BKK;           // 64
    issue(0, 0);

    for (int t = 0; t < NT; ++t) {
        const int cur = t & 1;
        if (t + 1 < NT) {
            issue(cur ^ 1, t + 1);
            asm volatile("cp.async.wait_group 1;\n");
        } else {
            asm volatile("cp.async.wait_group 0;\n");
        }
        __syncthreads();

        const uint32_t aH = baseAH + cur*ASZ*2, aL = baseAL + cur*ASZ*2;
        const uint32_t bH = baseBH + cur*BSZ*2, bL = baseBL + cur*BSZ*2;

        #pragma unroll
        for (int ks = 0; ks < 2; ks++) {
            uint32_t ah[4][4], al[4][4];
            #pragma unroll
            for (int mt = 0; mt < 4; mt++) {
                int chunk = (ks*2 + hc) ^ swzA[mt];
                uint32_t ad = rowA[mt]*64 + chunk*16;    // bytes: 32 bf16/row
                LDSM4(ah[mt][0], ah[mt][1], ah[mt][2], ah[mt][3], aH + ad);
                LDSM4(al[mt][0], al[mt][1], al[mt][2], al[mt][3], aL + ad);
            }
            const int krow = ks*16 + lr;
            #pragma unroll
            for (int nt = 0; nt < 4; nt++) {
                int chunk = (ncbase + nt) ^ swzB;
                uint32_t bd = krow*256 + chunk*16;       // bytes: 128 bf16/row
                uint32_t bh0, bh1, bl0, bl1;
                LDSM2T(bh0, bh1, bH + bd);
                LDSM2T(bl0, bl1, bL + bd);
                #pragma unroll
                for (int mt = 0; mt < 4; mt++) {
                    MMA16816(acc[mt][nt][0],acc[mt][nt][1],acc[mt][nt][2],acc[mt][nt][3],
                             ah[mt][0],ah[mt][1],ah[mt][2],ah[mt][3], bh0,bh1);
                    MMA16816(acc[mt][nt][0],acc[mt][nt][1],acc[mt][nt][2],acc[mt][nt][3],
                             ah[mt][0],ah[mt][1],ah[mt][2],ah[mt][3], bl0,bl1);
                    MMA16816(acc[mt][nt][0],acc[mt][nt][1],acc[mt][nt][2],acc[mt][nt][3],
                             al[mt][0],al[mt][1],al[mt][2],al[mt][3], bh0,bh1);
                }
            }
        }
        __syncthreads();
    }

    // ---- epilogue ----
    const int g  = lane >> 2;
    const int tg = lane & 3;
    #pragma unroll
    for (int nt = 0; nt < 4; nt++) {
        const int col = bn*BN + nwarp + nt*8 + tg*2;
        const float b0 = bias[col], b1 = bias[col+1];
        #pragma unroll
        for (int mt = 0; mt < 4; mt++) {
            const int row0 = bm*BM + mwarp + mt*16 + g;
            float v0 = acc[mt][nt][0] + b0, v1 = acc[mt][nt][1] + b1;
            float v2 = acc[mt][nt][2] + b0, v3 = acc[mt][nt][3] + b1;
            if (GELU) { v0 = geluf(v0); v1 = geluf(v1); v2 = geluf(v2); v3 = geluf(v3); }
            *(float2*)(C + (size_t)row0*NN + col)     = make_float2(v0, v1);
            *(float2*)(C + (size_t)(row0+8)*NN + col) = make_float2(v2, v3);
        }
    }
}

// ---------------- kernel 3: filt dots + tanh per (b,s) ---------------------
__global__ void filt_kernel(const float* __restrict__ fw,
                            const float* __restrict__ fb)
{
    const int bs = blockIdx.x;
    const float* hr = g_h + (size_t)bs * DD;

    float a[6] = {0.f,0.f,0.f,0.f,0.f,0.f};
    for (int i = threadIdx.x; i < DI; i += blockDim.x) {
        float w0 = fw[i*3+0], w1 = fw[i*3+1], w2 = fw[i*3+2];
        float h0 = hr[i];
        float h1 = hr[i + DI];
        a[0] += h0*w0; a[1] += h0*w1; a[2] += h0*w2;
        a[3] += h1*w0; a[4] += h1*w1; a[5] += h1*w2;
    }
    #pragma unroll
    for (int off = 16; off; off >>= 1)
        #pragma unroll
        for (int q = 0; q < 6; q++)
            a[q] += __shfl_xor_sync(0xffffffffu, a[q], off);

    __shared__ float red[8][6];
    int warp = threadIdx.x >> 5, lane = threadIdx.x & 31;
    if (lane == 0)
        #pragma unroll
        for (int q = 0; q < 6; q++) red[warp][q] = a[q];
    __syncthreads();

    if (threadIdx.x == 0) {
        float tsum[6];
        #pragma unroll
        for (int q = 0; q < 6; q++) {
            float s = 0.f;
            #pragma unroll
            for (int w = 0; w < 8; w++) s += red[w][q];
            tsum[q] = s;
        }
        #pragma unroll
        for (int k = 0; k < 3; k++)
            g_fs[(size_t)bs*3 + k] = tanhf(tsum[k] + fb[k]) + tanhf(tsum[3+k] + fb[k]);
    }
}

// ---------------- kernel 4: per-batch mean -> w[b][k] ----------------------
__global__ void wreduce_kernel()
{
    const int b = blockIdx.x;
    float a0 = 0.f, a1 = 0.f, a2 = 0.f;
    for (int s = threadIdx.x; s < SS; s += blockDim.x) {
        size_t p = ((size_t)b * SS + s) * 3;
        a0 += g_fs[p+0]; a1 += g_fs[p+1]; a2 += g_fs[p+2];
    }
    #pragma unroll
    for (int off = 16; off; off >>= 1) {
        a0 += __shfl_xor_sync(0xffffffffu, a0, off);
        a1 += __shfl_xor_sync(0xffffffffu, a1, off);
        a2 += __shfl_xor_sync(0xffffffffu, a2, off);
    }
    __shared__ float red[8][3];
    int warp = threadIdx.x >> 5, lane = threadIdx.x & 31;
    if (lane == 0) { red[warp][0] = a0; red[warp][1] = a1; red[warp][2] = a2; }
    __syncthreads();
    if (threadIdx.x == 0) {
        float s0 = 0.f, s1 = 0.f, s2 = 0.f;
        #pragma unroll
        for (int w = 0; w < 8; w++) { s0 += red[w][0]; s1 += red[w][1]; s2 += red[w][2]; }
        const float inv = 1.0f / (float)SS;
        g_w[b*3+0] = s0 * inv;
        g_w[b*3+1] = s1 * inv;
        g_w[b*3+2] = s2 * inv;
    }
}

// ---------------- kernel 5: gated conv * v, gelu -> y hi/lo ----------------
__global__ void convgate_kernel(const float* __restrict__ x)
{
    int idx = blockIdx.x * blockDim.x + threadIdx.x;
    if (idx >= BB * SS * D4) return;
    int d4 = idx % D4;
    int bs = idx / D4;
    int s  = bs & (SS - 1);
    int b  = bs >> 11;
    size_t base = (size_t)bs * DD + d4 * 4;

    float w0 = g_w[b*3+0], w1 = g_w[b*3+1], w2 = g_w[b*3+2];

    float c[3][4];   // [shift][elem], shift 0 = s-2, 1 = s-1, 2 = s
    #pragma unroll
    for (int sh = 0; sh < 3; sh++) {
        int soff = sh - 2;
        if (s + soff >= 0) {
            size_t p = base + (size_t)soff * DD;
            __nv_bfloat162 h0 = *(const __nv_bfloat162*)(g_x2h + p);
            __nv_bfloat162 h1 = *(const __nv_bfloat162*)(g_x2h + p + 2);
            __nv_bfloat162 l0 = *(const __nv_bfloat162*)(g_x2l + p);
            __nv_bfloat162 l1 = *(const __nv_bfloat162*)(g_x2l + p + 2);
            c[sh][0] = __bfloat162float(h0.x) + __bfloat162float(l0.x);
            c[sh][1] = __bfloat162float(h0.y) + __bfloat162float(l0.y);
            c[sh][2] = __bfloat162float(h1.x) + __bfloat162float(l1.x);
            c[sh][3] = __bfloat162float(h1.y) + __bfloat162float(l1.y);
        } else {
            c[sh][0] = c[sh][1] = c[sh][2] = c[sh][3] = 0.f;
        }
    }
    float4 v = *(const float4*)(x + base);
    const float vv[4] = {v.x, v.y, v.z, v.w};

    __nv_bfloat162 yh0, yh1, yl0, yl1;
    float o[4];
    #pragma unroll
    for (int q = 0; q < 4; q++)
        o[q] = geluf((c[0][q]*w0 + c[1][q]*w1 + c[2][q]*w2) * vv[q]);
    split2(o[0], yh0.x, yl0.x); split2(o[1], yh0.y, yl0.y);
    split2(o[2], yh1.x, yl1.x); split2(o[3], yh1.y, yl1.y);
    *(__nv_bfloat162*)(g_yh + base)     = yh0;
    *(__nv_bfloat162*)(g_yh + base + 2) = yh1;
    *(__nv_bfloat162*)(g_yl + base)     = yl0;
    *(__nv_bfloat162*)(g_yl + base + 2) = yl1;
}

// ---------------- launcher ---------------------------------------------------
extern "C" void kernel_launch(void* const* d_in, const int* in_sizes, int n_in,
                              void* d_out, int out_size)
{
    const float* x       = (const float*)d_in[0];
    const float* short_w = (const float*)d_in[1];
    const float* short_b = (const float*)d_in[2];
    const float* proj_w  = (const float*)d_in[3];
    const float* proj_b  = (const float*)d_in[4];
    const float* filt_w  = (const float*)d_in[5];
    const float* filt_b  = (const float*)d_in[6];
    const float* out_w   = (const float*)d_in[7];
    const float* out_b   = (const float*)d_in[8];
    float* out = (float*)d_out;

    __nv_bfloat16 *px2h, *px2l, *pyh, *pyl, *ppwh, *ppwl, *powh, *powl;
    float *ph;
    cudaGetSymbolAddress((void**)&px2h, g_x2h);
    cudaGetSymbolAddress((void**)&px2l, g_x2l);
    cudaGetSymbolAddress((void**)&ph,   g_h);
    cudaGetSymbolAddress((void**)&pyh,  g_yh);
    cudaGetSymbolAddress((void**)&pyl,  g_yl);
    cudaGetSymbolAddress((void**)&ppwh, g_pwh);
    cudaGetSymbolAddress((void**)&ppwl, g_pwl);
    cudaGetSymbolAddress((void**)&powh, g_owh);
    cudaGetSymbolAddress((void**)&powl, g_owl);

    const int smem_bytes = (4*ASZ + 4*BSZ) * 2;   // 64 KB
    cudaFuncSetAttribute(gemm_split<1>, cudaFuncAttributeMaxDynamicSharedMemorySize, smem_bytes);
    cudaFuncSetAttribute(gemm_split<0>, cudaFuncAttributeMaxDynamicSharedMemorySize, smem_bytes);

    const int ethreads = 256;
    const int eblocks  = (BB * SS * D4 + ethreads - 1) / ethreads;

    // weight conversions (independent of data path)
    {
        int n4 = (KK * NN) / 4;
        int blocks = (n4 + 255) / 256;
        convert_split_kernel<<<blocks, 256>>>(proj_w, ppwh, ppwl, n4);
        convert_split_kernel<<<blocks, 256>>>(out_w,  powh, powl, n4);
    }

    // 1. short conv residual -> x2 hi/lo
    shortconv_kernel<<<eblocks, ethreads>>>(x, short_w, short_b);

    // 2. h = gelu(x2 @ proj_w + proj_b)
    dim3 ggrid(NN / BN, MM / BM);   // (16, 64)
    gemm_split<1><<<ggrid, 256, smem_bytes>>>(px2h, px2l, ppwh, ppwl, proj_b, ph);

    // 3/4. filter weights
    filt_kernel<<<MM, 256>>>(filt_w, filt_b);
    wreduce_kernel<<<BB, 256>>>();

    // 5. y = gelu(conv(x2; w) * x) -> y hi/lo
    convgate_kernel<<<eblocks, ethreads>>>(x);

    // 6. out = y @ out_w + out_b
    gemm_split<0><<<ggrid, 256, smem_bytes>>>(pyh, pyl, powh, powl, out_b, out);
}

// round 4
// speedup vs baseline: 4.3427x; 1.7583x over previous
#include <cuda_runtime.h>
#include <cuda_fp16.h>
#include <math.h>
#include <stdint.h>

#define BB 4
#define SS 2048
#define DD 2048
#define DI 1024
#define MM (BB*SS)      // 8192
#define KK DD
#define NN DD
#define D4 (DD/4)

// GEMM tiling (same proven structure as R2)
#define BM 128
#define BN 128
#define BKK 32
#define ASZ (BM*BKK)    // 4096 fp16 elems per A stage buffer
#define BSZ (BKK*BN)    // 4096

// ---------------- scratch ---------------------------------------------------
__device__ __half g_x2[(size_t)MM*KK];    // x after short conv residual (fp16)
__device__ __half g_h [(size_t)MM*NN];    // h after GEMM1+gelu (fp16)
__device__ __half g_yh[(size_t)MM*KK];    // y hi (fp16)
__device__ __half g_yl[(size_t)MM*KK];    // y lo (fp16 residual)
__device__ __half g_pw[(size_t)KK*NN];    // proj_w fp16
__device__ __half g_ow[(size_t)KK*NN];    // out_w fp16
__device__ float g_fs[(size_t)MM*3];
__device__ float g_w [BB*3];

__device__ __forceinline__ float geluf(float v) {
    return 0.5f * v * (1.0f + erff(v * 0.70710678118654752f));
}
__device__ __forceinline__ void split2h(float v, __half& hi, __half& lo) {
    hi = __float2half_rn(v);
    lo = __float2half_rn(v - __half2float(hi));
}
__device__ __forceinline__ uint32_t smem_u32(const void* p) {
    return (uint32_t)__cvta_generic_to_shared(p);
}

#define CP16(s, g) asm volatile("cp.async.cg.shared.global [%0], [%1], 16;\n" :: "r"(s), "l"(g))
#define CP_COMMIT() asm volatile("cp.async.commit_group;\n")
#define LDSM4(R0,R1,R2,R3,addr) \
    asm volatile("ldmatrix.sync.aligned.m8n8.x4.shared.b16 {%0,%1,%2,%3},[%4];" \
                 : "=r"(R0),"=r"(R1),"=r"(R2),"=r"(R3) : "r"(addr))
#define LDSM2T(R0,R1,addr) \
    asm volatile("ldmatrix.sync.aligned.m8n8.x2.trans.shared.b16 {%0,%1},[%2];" \
                 : "=r"(R0),"=r"(R1) : "r"(addr))
#define MMAH16816(D0,D1,D2,D3,A0,A1,A2,A3,B0,B1) \
    asm volatile("mma.sync.aligned.m16n8k16.row.col.f32.f16.f16.f32 " \
                 "{%0,%1,%2,%3},{%4,%5,%6,%7},{%8,%9},{%0,%1,%2,%3};" \
                 : "+f"(D0),"+f"(D1),"+f"(D2),"+f"(D3) \
                 : "r"(A0),"r"(A1),"r"(A2),"r"(A3),"r"(B0),"r"(B1))

// ---------------- kernel 1: short conv + residual -> x2 (fp16) -------------
__global__ void shortconv_kernel(const float* __restrict__ x,
                                 const float* __restrict__ sw,
                                 const float* __restrict__ sb)
{
    int idx = blockIdx.x * blockDim.x + threadIdx.x;
    if (idx >= BB * SS * D4) return;
    int d4 = idx % D4;
    int bs = idx / D4;
    int s  = bs & (SS - 1);
    int d  = d4 * 4;
    size_t base = (size_t)bs * DD + d;

    float4 xc = *(const float4*)(x + base);
    float4 x1 = (s >= 1) ? *(const float4*)(x + base - DD)   : make_float4(0.f,0.f,0.f,0.f);
    float4 x0 = (s >= 2) ? *(const float4*)(x + base - 2*DD) : make_float4(0.f,0.f,0.f,0.f);

    float o[4];
    const float xcv[4] = {xc.x, xc.y, xc.z, xc.w};
    const float x1v[4] = {x1.x, x1.y, x1.z, x1.w};
    const float x0v[4] = {x0.x, x0.y, x0.z, x0.w};
    #pragma unroll
    for (int q = 0; q < 4; q++) {
        float w0 = sw[(d+q)*3+0], w1 = sw[(d+q)*3+1], w2 = sw[(d+q)*3+2];
        o[q] = xcv[q] + sb[d+q] + x0v[q]*w0 + x1v[q]*w1 + xcv[q]*w2;
    }
    *(__half2*)(g_x2 + base)     = __floats2half2_rn(o[0], o[1]);
    *(__half2*)(g_x2 + base + 2) = __floats2half2_rn(o[2], o[3]);
}

// ---------------- weight conversion fp32 -> fp16 ----------------------------
__global__ void convert_half_kernel(const float* __restrict__ src,
                                    __half* __restrict__ dst, int n4)
{
    int i = blockIdx.x * blockDim.x + threadIdx.x;
    if (i >= n4) return;
    size_t base = (size_t)i * 4;
    float4 v = *(const float4*)(src + base);
    *(__half2*)(dst + base)     = __floats2half2_rn(v.x, v.y);
    *(__half2*)(dst + base + 2) = __floats2half2_rn(v.z, v.w);
}

// ---------------- fp16 tensor-core GEMM -------------------------------------
// C = (Ah [+ Al]) @ B + bias (+GELU).  A: MxK row-major fp16 (hi[, lo]),
// B: KxN row-major fp16, C: fp32 or fp16 per OUTHALF.
template<int GELU, int SPLITA, int OUTHALF>
__global__ void __launch_bounds__(256)
gemm_h(const __half* __restrict__ Ahi, const __half* __restrict__ Alo,
       const __half* __restrict__ B, const float* __restrict__ bias,
       void* __restrict__ Cv)
{
    extern __shared__ __half sm[];
    __half* AsH = sm;                                   // [2][128][32]
    __half* AsL = SPLITA ? (sm + 2*ASZ) : nullptr;
    __half* Bs  = sm + (SPLITA ? 4 : 2)*ASZ;            // [2][32][128]

    const int tid  = threadIdx.x;
    const int bm   = blockIdx.y, bn = blockIdx.x;
    const int warp = tid >> 5, lane = tid & 31;
    const int mwarp = (warp & 1) * 64;
    const int nwarp = (warp >> 1) * 32;

    const int a_m = tid >> 2;
    const int a_c = tid & 3;
    const int b_k = tid >> 4;
    const int b_c = tid & 15;

    const __half* gAh = Ahi + ((size_t)(bm*BM + a_m))*KK + a_c*8;
    const __half* gAl = SPLITA ? (Alo + ((size_t)(bm*BM + a_m))*KK + a_c*8) : nullptr;
    const __half* gB  = B + (size_t)b_k*NN + bn*BN + b_c*8;

    const int sA0 = (a_m*BKK      + ((a_c ^ (a_m&3))*8)) * 2;
    const int sA1 = ((a_m+64)*BKK + ((a_c ^ (a_m&3))*8)) * 2;
    const int sB0 = (b_k*BN       + ((b_c ^ (b_k&7))*8)) * 2;
    const int sB1 = ((b_k+16)*BN  + ((b_c ^ (b_k&7))*8)) * 2;

    const uint32_t baseAH = smem_u32(AsH);
    const uint32_t baseAL = SPLITA ? smem_u32(AsL) : 0;
    const uint32_t baseB  = smem_u32(Bs);

    auto issue = [&](int stg, int t) {
        const size_t koffA = (size_t)t * BKK;
        const size_t koffB = (size_t)t * BKK * NN;
        uint32_t aH = baseAH + stg*ASZ*2;
        uint32_t bS = baseB  + stg*BSZ*2;
        CP16(aH + sA0, gAh + koffA);
        CP16(aH + sA1, gAh + koffA + (size_t)64*KK);
        if (SPLITA) {
            uint32_t aL = baseAL + stg*ASZ*2;
            CP16(aL + sA0, gAl + koffA);
            CP16(aL + sA1, gAl + koffA + (size_t)64*KK);
        }
        CP16(bS + sB0, gB + koffB);
        CP16(bS + sB1, gB + koffB + (size_t)16*NN);
        CP_COMMIT();
    };

    float acc[4][4][4];
    #pragma unroll
    for (int i = 0; i < 4; i++)
        #pragma unroll
        for (int j = 0; j < 4; j++)
            #pragma unroll
            for (int q = 0; q < 4; q++) acc[i][j][q] = 0.f;

    const int lr = lane & 15;
    const int hc = lane >> 4;
    int rowA[4], swzA[4];
    #pragma unroll
    for (int mt = 0; mt < 4; mt++) {
        rowA[mt] = mwarp + mt*16 + lr;
        swzA[mt] = rowA[mt] & 3;
    }
    const int swzB = lr & 7;
    const int ncbase = nwarp >> 3;

    const int NT = KK / BKK;
    issue(0, 0);

    for (int t = 0; t < NT; ++t) {
        const int cur = t & 1;
        if (t + 1 < NT) {
            issue(cur ^ 1, t + 1);
            asm volatile("cp.async.wait_group 1;\n");
        } else {
            asm volatile("cp.async.wait_group 0;\n");
        }
        __syncthreads();

        const uint32_t aH = baseAH + cur*ASZ*2;
        const uint32_t aL = SPLITA ? (baseAL + cur*ASZ*2) : 0;
        const uint32_t bS = baseB  + cur*BSZ*2;

        #pragma unroll
        for (int ks = 0; ks < 2; ks++) {
            uint32_t ah[4][4], al[4][4];
            #pragma unroll
            for (int mt = 0; mt < 4; mt++) {
                int chunk = (ks*2 + hc) ^ swzA[mt];
                uint32_t ad = rowA[mt]*64 + chunk*16;
                LDSM4(ah[mt][0], ah[mt][1], ah[mt][2], ah[mt][3], aH + ad);
                if (SPLITA) LDSM4(al[mt][0], al[mt][1], al[mt][2], al[mt][3], aL + ad);
            }
            const int krow = ks*16 + lr;
            #pragma unroll
            for (int nt = 0; nt < 4; nt++) {
                int chunk = (ncbase + nt) ^ swzB;
                uint32_t bd = krow*256 + chunk*16;
                uint32_t b0, b1;
                LDSM2T(b0, b1, bS + bd);
                #pragma unroll
                for (int mt = 0; mt < 4; mt++) {
                    MMAH16816(acc[mt][nt][0],acc[mt][nt][1],acc[mt][nt][2],acc[mt][nt][3],
                              ah[mt][0],ah[mt][1],ah[mt][2],ah[mt][3], b0,b1);
                    if (SPLITA)
                        MMAH16816(acc[mt][nt][0],acc[mt][nt][1],acc[mt][nt][2],acc[mt][nt][3],
                                  al[mt][0],al[mt][1],al[mt][2],al[mt][3], b0,b1);
                }
            }
        }
        __syncthreads();
    }

    // ---- epilogue ----
    const int g  = lane >> 2;
    const int tg = lane & 3;
    #pragma unroll
    for (int nt = 0; nt < 4; nt++) {
        const int col = bn*BN + nwarp + nt*8 + tg*2;
        const float b0 = bias[col], b1 = bias[col+1];
        #pragma unroll
        for (int mt = 0; mt < 4; mt++) {
            const int row0 = bm*BM + mwarp + mt*16 + g;
            float v0 = acc[mt][nt][0] + b0, v1 = acc[mt][nt][1] + b1;
            float v2 = acc[mt][nt][2] + b0, v3 = acc[mt][nt][3] + b1;
            if (GELU) { v0 = geluf(v0); v1 = geluf(v1); v2 = geluf(v2); v3 = geluf(v3); }
            if (OUTHALF) {
                __half* C = (__half*)Cv;
                *(__half2*)(C + (size_t)row0*NN + col)     = __floats2half2_rn(v0, v1);
                *(__half2*)(C + (size_t)(row0+8)*NN + col) = __floats2half2_rn(v2, v3);
            } else {
                float* C = (float*)Cv;
                *(float2*)(C + (size_t)row0*NN + col)     = make_float2(v0, v1);
                *(float2*)(C + (size_t)(row0+8)*NN + col) = make_float2(v2, v3);
            }
        }
    }
}

// ---------------- kernel 3: filt dots + tanh per (b,s) ---------------------
__global__ void filt_kernel(const float* __restrict__ fw,
                            const float* __restrict__ fb)
{
    const int bs = blockIdx.x;
    const __half* hr = g_h + (size_t)bs * DD;

    float a[6] = {0.f,0.f,0.f,0.f,0.f,0.f};
    for (int i = threadIdx.x*2; i < DI; i += blockDim.x*2) {
        __half2 p0 = *(const __half2*)(hr + i);
        __half2 p1 = *(const __half2*)(hr + i + DI);
        float h00 = __low2float(p0), h01 = __high2float(p0);
        float h10 = __low2float(p1), h11 = __high2float(p1);
        float wa0 = fw[i*3+0], wa1 = fw[i*3+1], wa2 = fw[i*3+2];
        float wb0 = fw[i*3+3], wb1 = fw[i*3+4], wb2 = fw[i*3+5];
        a[0] += h00*wa0 + h01*wb0;
        a[1] += h00*wa1 + h01*wb1;
        a[2] += h00*wa2 + h01*wb2;
        a[3] += h10*wa0 + h11*wb0;
        a[4] += h10*wa1 + h11*wb1;
        a[5] += h10*wa2 + h11*wb2;
    }
    #pragma unroll
    for (int off = 16; off; off >>= 1)
        #pragma unroll
        for (int q = 0; q < 6; q++)
            a[q] += __shfl_xor_sync(0xffffffffu, a[q], off);

    __shared__ float red[8][6];
    int warp = threadIdx.x >> 5, lane = threadIdx.x & 31;
    if (lane == 0)
        #pragma unroll
        for (int q = 0; q < 6; q++) red[warp][q] = a[q];
    __syncthreads();

    if (threadIdx.x == 0) {
        float tsum[6];
        #pragma unroll
        for (int q = 0; q < 6; q++) {
            float s = 0.f;
            #pragma unroll
            for (int w = 0; w < 8; w++) s += red[w][q];
            tsum[q] = s;
        }
        #pragma unroll
        for (int k = 0; k < 3; k++)
            g_fs[(size_t)bs*3 + k] = tanhf(tsum[k] + fb[k]) + tanhf(tsum[3+k] + fb[k]);
    }
}

// ---------------- kernel 4: per-batch mean -> w[b][k] ----------------------
__global__ void wreduce_kernel()
{
    const int b = blockIdx.x;
    float a0 = 0.f, a1 = 0.f, a2 = 0.f;
    for (int s = threadIdx.x; s < SS; s += blockDim.x) {
        size_t p = ((size_t)b * SS + s) * 3;
        a0 += g_fs[p+0]; a1 += g_fs[p+1]; a2 += g_fs[p+2];
    }
    #pragma unroll
    for (int off = 16; off; off >>= 1) {
        a0 += __shfl_xor_sync(0xffffffffu, a0, off);
        a1 += __shfl_xor_sync(0xffffffffu, a1, off);
        a2 += __shfl_xor_sync(0xffffffffu, a2, off);
    }
    __shared__ float red[8][3];
    int warp = threadIdx.x >> 5, lane = threadIdx.x & 31;
    if (lane == 0) { red[warp][0] = a0; red[warp][1] = a1; red[warp][2] = a2; }
    __syncthreads();
    if (threadIdx.x == 0) {
        float s0 = 0.f, s1 = 0.f, s2 = 0.f;
        #pragma unroll
        for (int w = 0; w < 8; w++) { s0 += red[w][0]; s1 += red[w][1]; s2 += red[w][2]; }
        const float inv = 1.0f / (float)SS;
        g_w[b*3+0] = s0 * inv;
        g_w[b*3+1] = s1 * inv;
        g_w[b*3+2] = s2 * inv;
    }
}

// ---------------- kernel 5: gated conv * v, gelu -> y hi/lo (fp16) ---------
__global__ void convgate_kernel(const float* __restrict__ x)
{
    int idx = blockIdx.x * blockDim.x + threadIdx.x;
    if (idx >= BB * SS * D4) return;
    int d4 = idx % D4;
    int bs = idx / D4;
    int s  = bs & (SS - 1);
    int b  = bs >> 11;
    size_t base = (size_t)bs * DD + d4 * 4;

    float w0 = g_w[b*3+0], w1 = g_w[b*3+1], w2 = g_w[b*3+2];

    float c[3][4];
    #pragma unroll
    for (int sh = 0; sh < 3; sh++) {
        int soff = sh - 2;
        if (s + soff >= 0) {
            size_t p = base + (size_t)soff * DD;
            __half2 p0 = *(const __half2*)(g_x2 + p);
            __half2 p1 = *(const __half2*)(g_x2 + p + 2);
            c[sh][0] = __low2float(p0); c[sh][1] = __high2float(p0);
            c[sh][2] = __low2float(p1); c[sh][3] = __high2float(p1);
        } else {
            c[sh][0] = c[sh][1] = c[sh][2] = c[sh][3] = 0.f;
        }
    }
    float4 v = *(const float4*)(x + base);
    const float vv[4] = {v.x, v.y, v.z, v.w};

    __half yh[4], yl[4];
    #pragma unroll
    for (int q = 0; q < 4; q++) {
        float o = geluf((c[0][q]*w0 + c[1][q]*w1 + c[2][q]*w2) * vv[q]);
        split2h(o, yh[q], yl[q]);
    }
    *(__half2*)(g_yh + base)     = __halves2half2(yh[0], yh[1]);
    *(__half2*)(g_yh + base + 2) = __halves2half2(yh[2], yh[3]);
    *(__half2*)(g_yl + base)     = __halves2half2(yl[0], yl[1]);
    *(__half2*)(g_yl + base + 2) = __halves2half2(yl[2], yl[3]);
}

// ---------------- launcher ---------------------------------------------------
extern "C" void kernel_launch(void* const* d_in, const int* in_sizes, int n_in,
                              void* d_out, int out_size)
{
    const float* x       = (const float*)d_in[0];
    const float* short_w = (const float*)d_in[1];
    const float* short_b = (const float*)d_in[2];
    const float* proj_w  = (const float*)d_in[3];
    const float* proj_b  = (const float*)d_in[4];
    const float* filt_w  = (const float*)d_in[5];
    const float* filt_b  = (const float*)d_in[6];
    const float* out_w   = (const float*)d_in[7];
    const float* out_b   = (const float*)d_in[8];
    float* out = (float*)d_out;

    __half *px2, *ph, *pyh, *pyl, *ppw, *pow_;
    cudaGetSymbolAddress((void**)&px2, g_x2);
    cudaGetSymbolAddress((void**)&ph,  g_h);
    cudaGetSymbolAddress((void**)&pyh, g_yh);
    cudaGetSymbolAddress((void**)&pyl, g_yl);
    cudaGetSymbolAddress((void**)&ppw, g_pw);
    cudaGetSymbolAddress((void**)&pow_, g_ow);

    const int smem1 = (2*ASZ + 2*BSZ) * 2;   // 32 KB (SPLITA=0)
    const int smem2 = (4*ASZ + 2*BSZ) * 2;   // 48 KB (SPLITA=1)
    cudaFuncSetAttribute((const void*)gemm_h<1,0,1>, cudaFuncAttributeMaxDynamicSharedMemorySize, smem1);
    cudaFuncSetAttribute((const void*)gemm_h<0,1,0>, cudaFuncAttributeMaxDynamicSharedMemorySize, smem2);

    const int ethreads = 256;
    const int eblocks  = (BB * SS * D4 + ethreads - 1) / ethreads;

    // weight conversions
    {
        int n4 = (KK * NN) / 4;
        int blocks = (n4 + 255) / 256;
        convert_half_kernel<<<blocks, 256>>>(proj_w, ppw, n4);
        convert_half_kernel<<<blocks, 256>>>(out_w,  pow_, n4);
    }

    // 1. short conv residual -> x2 (fp16)
    shortconv_kernel<<<eblocks, ethreads>>>(x, short_w, short_b);

    // 2. h = gelu(x2 @ proj_w + proj_b)  — single-pass fp16, fp16 out
    dim3 ggrid(NN / BN, MM / BM);   // (16, 64)
    gemm_h<1,0,1><<<ggrid, 256, smem1>>>(px2, nullptr, ppw, proj_b, ph);

    // 3/4. filter weights
    filt_kernel<<<MM, 256>>>(filt_w, filt_b);
    wreduce_kernel<<<BB, 256>>>();

    // 5. y = gelu(conv(x2; w) * x) -> y hi/lo fp16
    convgate_kernel<<<eblocks, ethreads>>>(x);

    // 6. out = y @ out_w + out_b — 2-term split-A fp16, fp32 out
    gemm_h<0,1,0><<<ggrid, 256, smem2>>>(pyh, pyl, pow_, out_b, out);
}